// round 15
// baseline (speedup 1.0000x reference)
#include <cuda_runtime.h>
#include <cuda_bf16.h>
#include <cuda_fp16.h>
#include <math.h>
#include <stdint.h>

#define N_NODES  100000
#define N_EDGES  1600000
#define N_GRAPHS 2048
#define H        256
#define K1       128
#define NCLS     64
#define NB_SCAN  ((N_NODES + 255) / 256)   // 391

// ---------------- scratch (device globals; zero-initialized at load) -------
__device__ int   g_degi[N_NODES];
__device__ int   g_rowptr[N_NODES + 1];
__device__ int   g_cur[N_NODES];
__device__ volatile unsigned long long g_scanst[NB_SCAN];  // lookback state
__device__ float g_dinv[N_NODES];
__device__ int2  g_edge[N_EDGES];                  // {src*32, norm as int}
__device__ __half g_xh [(size_t)N_NODES * K1];     // fp16 copy of x
__device__ __half g_act1h[(size_t)N_NODES * H];    // fp16 act1
__device__ __nv_bfloat16 g_a1h[(size_t)N_NODES * K1];
__device__ __nv_bfloat16 g_a1l[(size_t)N_NODES * K1];
__device__ __nv_bfloat16 g_a2h[(size_t)N_NODES * H];
__device__ __nv_bfloat16 g_a2l[(size_t)N_NODES * H];
__device__ __nv_bfloat16 g_w1h[H * K1];
__device__ __nv_bfloat16 g_w1l[H * K1];
__device__ __nv_bfloat16 g_w2h[H * H];
__device__ __nv_bfloat16 g_w2l[H * H];
__device__ float g_sums[N_GRAPHS * H];

__device__ __forceinline__ uint32_t s2u(const void* p) {
    return (uint32_t)__cvta_generic_to_shared(p);
}
__device__ __forceinline__ void cpa16(uint32_t dst, const void* src, int nbytes) {
    asm volatile("cp.async.cg.shared.global [%0], [%1], 16, %2;"
                 :: "r"(dst), "l"(src), "r"(nbytes));
}

// ---------------- #1: degree histogram + x->fp16 (full occupancy) ------------
__global__ void deg_kernel(const int* __restrict__ ei, const float* __restrict__ x) {
    int e = blockIdx.x * blockDim.x + threadIdx.x;
    if (e < N_EDGES) atomicAdd(&g_degi[ei[N_EDGES + e]], 1);
    for (int t = e; t < N_NODES * (K1 / 4); t += N_EDGES) {
        float4 v = ((const float4*)x)[t];
        __half2 a = __floats2half2_rn(v.x, v.y);
        __half2 b = __floats2half2_rn(v.z, v.w);
        ((uint2*)g_xh)[t] = make_uint2(*(uint32_t*)&a, *(uint32_t*)&b);
    }
}

// ---------------- #2: single-pass scan (decoupled lookback) + dinv -----------
__global__ void scan_kernel() {
    __shared__ int sh[256];
    __shared__ int s_pref;
    int b = blockIdx.x, t = threadIdx.x;
    int i = b * 256 + t;
    int v = (i < N_NODES) ? g_degi[i] : 0;
    if (i < N_NODES) g_dinv[i] = rsqrtf((float)(v + 1));
    sh[t] = v;
    __syncthreads();
    for (int off = 1; off < 256; off <<= 1) {
        int tmp = (t >= off) ? sh[t - off] : 0;
        __syncthreads();
        sh[t] += tmp;
        __syncthreads();
    }
    int excl = sh[t] - v;
    if (t == 255) {
        int total = sh[255];
        if (b == 0) {
            g_scanst[0] = ((unsigned long long)total << 2) | 2ull;
            __threadfence();
            s_pref = 0;
        } else {
            g_scanst[b] = ((unsigned long long)total << 2) | 1ull;
            __threadfence();
            int sum = 0;
            for (int p = b - 1; p >= 0; ) {
                unsigned long long s;
                do { s = g_scanst[p]; } while ((s & 3ull) == 0ull);
                sum += (int)(s >> 2);
                if ((s & 3ull) == 2ull) break;
                p--;
            }
            g_scanst[b] = ((unsigned long long)(sum + total) << 2) | 2ull;
            __threadfence();
            s_pref = sum;
        }
    }
    __syncthreads();
    if (i < N_NODES) {
        int r = s_pref + excl;
        g_rowptr[i] = r;
        g_cur[i] = r;
    }
    if (i == 0) g_rowptr[N_NODES] = N_EDGES;
}

// ---------------- #3: CSR fill (packed, pre-scaled edge records) -------------
__global__ void fill_kernel(const int* __restrict__ ei) {
    int e = blockIdx.x * blockDim.x + threadIdx.x;
    if (e >= N_EDGES) return;
    int s = ei[e];
    int d = ei[N_EDGES + e];
    int pos = atomicAdd(&g_cur[d], 1);
    float nrm = g_dinv[s] * g_dinv[d];
    g_edge[pos] = make_int2(s * 32, __float_as_int(nrm));
}

// ---------------- weight transposes + bf16 hi/lo splits ----------------------
__global__ void wsplit_kernel(const float* __restrict__ W1,
                              const float* __restrict__ W2) {
    int idx = blockIdx.x * blockDim.x + threadIdx.x;
    const float* W;
    __nv_bfloat16 *Wh, *Wl;
    int K, local;
    if (idx < K1 * H) { W = W1; Wh = g_w1h; Wl = g_w1l; K = K1; local = idx; }
    else if (idx < K1 * H + H * H) {
        W = W2; Wh = g_w2h; Wl = g_w2l; K = H; local = idx - K1 * H;
    } else return;
    int k = local / H, n = local % H;
    float w = W[local];
    __nv_bfloat16 hi = __float2bfloat16_rn(w);
    float lo = w - __bfloat162float(hi);
    Wh[n * K + k] = hi;
    Wl[n * K + k] = __float2bfloat16_rn(lo);
}

// ---------------- split helpers ----------------------------------------------
__device__ __forceinline__ void split4(float4 v, uint2& hi, uint2& lo) {
    __nv_bfloat16 hx = __float2bfloat16_rn(v.x);
    __nv_bfloat16 hy = __float2bfloat16_rn(v.y);
    __nv_bfloat16 hz = __float2bfloat16_rn(v.z);
    __nv_bfloat16 hw = __float2bfloat16_rn(v.w);
    __nv_bfloat162 h01 = __halves2bfloat162(hx, hy);
    __nv_bfloat162 h23 = __halves2bfloat162(hz, hw);
    __nv_bfloat162 l01 = __halves2bfloat162(
        __float2bfloat16_rn(v.x - __bfloat162float(hx)),
        __float2bfloat16_rn(v.y - __bfloat162float(hy)));
    __nv_bfloat162 l23 = __halves2bfloat162(
        __float2bfloat16_rn(v.z - __bfloat162float(hz)),
        __float2bfloat16_rn(v.w - __bfloat162float(hw)));
    hi = make_uint2(*(uint32_t*)&h01, *(uint32_t*)&h23);
    lo = make_uint2(*(uint32_t*)&l01, *(uint32_t*)&l23);
}

__device__ __forceinline__ float4 h4_to_f4(uint2 u) {
    __half2 a = *(__half2*)&u.x;
    __half2 b = *(__half2*)&u.y;
    float2 fa = __half22float2(a);
    float2 fb = __half22float2(b);
    return make_float4(fa.x, fa.y, fb.x, fb.y);
}

// ---------------- #4: aggregation 1 (width 128, 8 edges in flight) -----------
__global__ __launch_bounds__(256, 8) void agg1_kernel() {
    int node = blockIdx.x * 8 + (threadIdx.x >> 5);
    if (node >= N_NODES) return;
    int lane = threadIdx.x & 31;
    const uint2* Xl = (const uint2*)g_xh + lane;   // lane offset hoisted

    float di = g_dinv[node];
    float sl = di * di;
    float4 a = h4_to_f4(Xl[node * 32]);
    float4 acc = make_float4(a.x * sl, a.y * sl, a.z * sl, a.w * sl);

    int i = g_rowptr[node], end = g_rowptr[node + 1];
    for (; i + 8 <= end; i += 8) {
        uint2 u[8];
        float w[8];
        #pragma unroll
        for (int q = 0; q < 8; q++) {
            int2 e = g_edge[i + q];        // one LDG.64: {src*32, norm}
            w[q] = __int_as_float(e.y);
            u[q] = Xl[e.x];
        }
        #pragma unroll
        for (int q = 0; q < 8; q++) {
            float4 v = h4_to_f4(u[q]);
            acc.x += v.x * w[q]; acc.y += v.y * w[q];
            acc.z += v.z * w[q]; acc.w += v.w * w[q];
        }
    }
    for (; i < end; i++) {
        int2 e = g_edge[i];
        float w = __int_as_float(e.y);
        float4 v = h4_to_f4(Xl[e.x]);
        acc.x += v.x*w; acc.y += v.y*w; acc.z += v.z*w; acc.w += v.w*w;
    }
    uint2 hi, lo;
    split4(acc, hi, lo);
    ((uint2*)g_a1h)[(size_t)node * 32 + lane] = hi;
    ((uint2*)g_a1l)[(size_t)node * 32 + lane] = lo;
}

// ---------------- aggregation 2: two warp-tasks per node (agg1-style) --------
// task = node*2 + half; each task owns 128 of the 256 features.
__global__ __launch_bounds__(256, 8) void agg2_kernel() {
    int task = blockIdx.x * 8 + (threadIdx.x >> 5);
    if (task >= N_NODES * 2) return;
    int node = task >> 1;
    int lane = threadIdx.x & 31;
    // uint2 view of act1h: row stride 64; this task's column block:
    const uint2* Xl = (const uint2*)g_act1h + (task & 1) * 32 + lane;

    float di = g_dinv[node];
    float sl = di * di;
    float4 a = h4_to_f4(Xl[(size_t)node * 64]);
    float4 acc = make_float4(a.x * sl, a.y * sl, a.z * sl, a.w * sl);

    int i = g_rowptr[node], end = g_rowptr[node + 1];
    for (; i + 8 <= end; i += 8) {
        uint2 u[8];
        float w[8];
        #pragma unroll
        for (int q = 0; q < 8; q++) {
            int2 e = g_edge[i + q];
            w[q] = __int_as_float(e.y);
            u[q] = Xl[(size_t)e.x * 2];   // e.x = src*32 -> uint2 row offset src*64
        }
        #pragma unroll
        for (int q = 0; q < 8; q++) {
            float4 v = h4_to_f4(u[q]);
            acc.x += v.x * w[q]; acc.y += v.y * w[q];
            acc.z += v.z * w[q]; acc.w += v.w * w[q];
        }
    }
    for (; i < end; i++) {
        int2 e = g_edge[i];
        float w = __int_as_float(e.y);
        float4 v = h4_to_f4(Xl[(size_t)e.x * 2]);
        acc.x += v.x*w; acc.y += v.y*w; acc.z += v.z*w; acc.w += v.w*w;
    }
    uint2 hi, lo;
    split4(acc, hi, lo);
    size_t o = (size_t)node * 64 + (task & 1) * 32 + lane;
    ((uint2*)g_a2h)[o] = hi;
    ((uint2*)g_a2l)[o] = lo;
}

// ---------------- bf16-split tensor-core GEMM (pipelined, mma.sync) ----------
#define ROWB 80
#define OFF_AL 10240
#define OFF_BH 20480
#define OFF_BL 30720
#define STAGE  40960

template <bool POOL>
__global__ __launch_bounds__(512, 1) void gemm_kernel(
    const __nv_bfloat16* __restrict__ Ahg,
    const __nv_bfloat16* __restrict__ Alg,
    const __nv_bfloat16* __restrict__ Wth,
    const __nv_bfloat16* __restrict__ Wtl,
    const float* __restrict__ bias,
    __half* __restrict__ outh,
    const int* __restrict__ batch,
    int M, int K)
{
    extern __shared__ __align__(16) char smem[];
    const uint32_t sbase = s2u(smem);

    const int tid  = threadIdx.x;
    const int lane = tid & 31;
    const int wid  = tid >> 5;
    const int wm   = wid & 3;
    const int wn   = wid >> 2;
    const int bm   = blockIdx.x * 128;
    const int bn   = blockIdx.y * 128;

    const int lrow = tid >> 2;
    const int lcc  = tid & 3;
    const int arow_g = bm + lrow;
    const int avalid = (arow_g < M) ? 16 : 0;

    float acc[2][4][4];
    #pragma unroll
    for (int i = 0; i < 2; i++)
        #pragma unroll
        for (int j = 0; j < 4; j++)
            #pragma unroll
            for (int l = 0; l < 4; l++) acc[i][j][l] = 0.0f;

    const int T = K / 32;

    auto load_stage = [&](int t, int s) {
        int kk = t * 32;
        uint32_t base = sbase + s * STAGE + lrow * ROWB + lcc * 16;
        cpa16(base,          Ahg + (size_t)arow_g * K + kk + lcc * 8, avalid);
        cpa16(base + OFF_AL, Alg + (size_t)arow_g * K + kk + lcc * 8, avalid);
        cpa16(base + OFF_BH, Wth + (size_t)(bn + lrow) * K + kk + lcc * 8, 16);
        cpa16(base + OFF_BL, Wtl + (size_t)(bn + lrow) * K + kk + lcc * 8, 16);
        asm volatile("cp.async.commit_group;");
    };

    load_stage(0, 0);

    const int grp = lane >> 3, lr = lane & 7;

    for (int t = 0; t < T; t++) {
        int cur = t & 1;
        if (t + 1 < T) {
            load_stage(t + 1, cur ^ 1);
            asm volatile("cp.async.wait_group 1;");
        } else {
            asm volatile("cp.async.wait_group 0;");
        }
        __syncthreads();

        uint32_t sA = sbase + cur * STAGE;
        uint32_t sB = sA + OFF_BH;

        #pragma unroll
        for (int ks = 0; ks < 2; ks++) {
            const int kb = ks * 32;
            uint32_t fah[2][4], fal[2][4], fbh[8], fbl[8];
            #pragma unroll
            for (int mt = 0; mt < 2; mt++) {
                int arow = wm * 32 + mt * 16 + lr + ((grp & 1) ? 8 : 0);
                uint32_t ad = sA + arow * ROWB + kb + ((grp & 2) ? 16 : 0);
                asm volatile("ldmatrix.sync.aligned.m8n8.x4.shared.b16 {%0,%1,%2,%3}, [%4];"
                             : "=r"(fah[mt][0]), "=r"(fah[mt][1]), "=r"(fah[mt][2]), "=r"(fah[mt][3])
                             : "r"(ad));
                asm volatile("ldmatrix.sync.aligned.m8n8.x4.shared.b16 {%0,%1,%2,%3}, [%4];"
                             : "=r"(fal[mt][0]), "=r"(fal[mt][1]), "=r"(fal[mt][2]), "=r"(fal[mt][3])
                             : "r"(ad + OFF_AL));
            }
            #pragma unroll
            for (int bp = 0; bp < 2; bp++) {
                int brow = wn * 32 + bp * 16 + lr + ((grp & 2) ? 8 : 0);
                uint32_t bd = sB + brow * ROWB + kb + ((grp & 1) ? 16 : 0);
                asm volatile("ldmatrix.sync.aligned.m8n8.x4.shared.b16 {%0,%1,%2,%3}, [%4];"
                             : "=r"(fbh[bp*4+0]), "=r"(fbh[bp*4+1]), "=r"(fbh[bp*4+2]), "=r"(fbh[bp*4+3])
                             : "r"(bd));
                asm volatile("ldmatrix.sync.aligned.m8n8.x4.shared.b16 {%0,%1,%2,%3}, [%4];"
                             : "=r"(fbl[bp*4+0]), "=r"(fbl[bp*4+1]), "=r"(fbl[bp*4+2]), "=r"(fbl[bp*4+3])
                             : "r"(bd + (OFF_BL - OFF_BH)));
            }
            #pragma unroll
            for (int mt = 0; mt < 2; mt++) {
                #pragma unroll
                for (int nt = 0; nt < 4; nt++) {
                    float* c = acc[mt][nt];
                    uint32_t b0 = fbh[nt*2], b1 = fbh[nt*2+1];
                    uint32_t l0 = fbl[nt*2], l1 = fbl[nt*2+1];
                    asm volatile("mma.sync.aligned.m16n8k16.row.col.f32.bf16.bf16.f32 "
                                 "{%0,%1,%2,%3}, {%4,%5,%6,%7}, {%8,%9}, {%0,%1,%2,%3};"
                                 : "+f"(c[0]), "+f"(c[1]), "+f"(c[2]), "+f"(c[3])
                                 : "r"(fah[mt][0]), "r"(fah[mt][1]), "r"(fah[mt][2]), "r"(fah[mt][3]),
                                   "r"(b0), "r"(b1));
                    asm volatile("mma.sync.aligned.m16n8k16.row.col.f32.bf16.bf16.f32 "
                                 "{%0,%1,%2,%3}, {%4,%5,%6,%7}, {%8,%9}, {%0,%1,%2,%3};"
                                 : "+f"(c[0]), "+f"(c[1]), "+f"(c[2]), "+f"(c[3])
                                 : "r"(fah[mt][0]), "r"(fah[mt][1]), "r"(fah[mt][2]), "r"(fah[mt][3]),
                                   "r"(l0), "r"(l1));
                    asm volatile("mma.sync.aligned.m16n8k16.row.col.f32.bf16.bf16.f32 "
                                 "{%0,%1,%2,%3}, {%4,%5,%6,%7}, {%8,%9}, {%0,%1,%2,%3};"
                                 : "+f"(c[0]), "+f"(c[1]), "+f"(c[2]), "+f"(c[3])
                                 : "r"(fal[mt][0]), "r"(fal[mt][1]), "r"(fal[mt][2]), "r"(fal[mt][3]),
                                   "r"(b0), "r"(b1));
                }
            }
        }
        __syncthreads();
    }

    const int qr = lane >> 2;
    const int qc = (lane & 3) * 2;
    #pragma unroll
    for (int mt = 0; mt < 2; mt++) {
        int row0 = bm + wm * 32 + mt * 16 + qr;
        int row1 = row0 + 8;
        int bt0 = 0, bt1 = 0;
        if (POOL) {
            bt0 = (row0 < M) ? batch[row0] : 0;
            bt1 = (row1 < M) ? batch[row1] : 0;
        }
        #pragma unroll
        for (int nt = 0; nt < 4; nt++) {
            int col = bn + wn * 32 + nt * 8 + qc;
            float bx = bias[col], by = bias[col + 1];
            float v00 = fmaxf(acc[mt][nt][0] + bx, 0.f);
            float v01 = fmaxf(acc[mt][nt][1] + by, 0.f);
            float v10 = fmaxf(acc[mt][nt][2] + bx, 0.f);
            float v11 = fmaxf(acc[mt][nt][3] + by, 0.f);
            if (POOL) {
                if (row0 < M) {
                    float* p = &g_sums[(size_t)bt0 * H + col];
                    asm volatile("red.global.add.v2.f32 [%0], {%1,%2};"
                                 :: "l"(p), "f"(v00), "f"(v01) : "memory");
                }
                if (row1 < M) {
                    float* p = &g_sums[(size_t)bt1 * H + col];
                    asm volatile("red.global.add.v2.f32 [%0], {%1,%2};"
                                 :: "l"(p), "f"(v10), "f"(v11) : "memory");
                }
            } else {
                if (row0 < M)
                    *(__half2*)&outh[(size_t)row0 * H + col] = __floats2half2_rn(v00, v01);
                if (row1 < M)
                    *(__half2*)&outh[(size_t)row1 * H + col] = __floats2half2_rn(v10, v11);
            }
        }
    }
}

// ---------------- classifier + log_softmax + cleanup (fused) -----------------
__device__ __forceinline__ int lbound(const int* __restrict__ a, int key) {
    int lo = 0, hi = N_NODES;
    while (lo < hi) {
        int m = (lo + hi) >> 1;
        if (a[m] < key) lo = m + 1; else hi = m;
    }
    return lo;
}

__global__ __launch_bounds__(64) void classifier_kernel(
    const float* __restrict__ Wc, const float* __restrict__ bc,
    const int* __restrict__ batch, float* __restrict__ out)
{
    int g = blockIdx.x;
    int t = threadIdx.x;
    __shared__ float gv[H];
    __shared__ float lg[NCLS];
    __shared__ int s_lo, s_hi;

    if (t == 0) s_lo = lbound(batch, g);
    if (t == 1) s_hi = lbound(batch, g + 1);

    for (int k = t; k < H; k += NCLS) gv[k] = g_sums[g * H + k];
    __syncthreads();

    float inv = 1.0f / fmaxf((float)(s_hi - s_lo), 1.0f);

    float acc = bc[t];
    #pragma unroll 8
    for (int k = 0; k < H; k++) acc += gv[k] * inv * Wc[k * NCLS + t];
    lg[t] = acc;
    __syncthreads();

    float m = -INFINITY;
    #pragma unroll
    for (int i = 0; i < NCLS; i++) m = fmaxf(m, lg[i]);
    float s = 0.0f;
    #pragma unroll
    for (int i = 0; i < NCLS; i++) s += expf(lg[i] - m);
    out[g * NCLS + t] = acc - m - logf(s);

    // ---- cleanup for next graph-replayed call ----
    for (int k = t; k < H; k += NCLS) g_sums[g * H + k] = 0.0f;
    int flat = g * NCLS + t;                 // 0 .. 131071
    if (flat < N_NODES) g_degi[flat] = 0;
    if (flat < NB_SCAN) g_scanst[flat] = 0ull;
}

// ---------------- launch ------------------------------------------------------
extern "C" void kernel_launch(void* const* d_in, const int* in_sizes, int n_in,
                              void* d_out, int out_size)
{
    const float* x     = (const float*)d_in[0];
    const int*   ei    = (const int*)d_in[1];
    const int*   batch = (const int*)d_in[2];
    const float* W1    = (const float*)d_in[3];
    const float* b1    = (const float*)d_in[4];
    const float* W2    = (const float*)d_in[5];
    const float* b2    = (const float*)d_in[6];
    const float* Wc    = (const float*)d_in[7];
    const float* bc    = (const float*)d_in[8];
    float* out = (float*)d_out;

    __half *p_act1h;
    __nv_bfloat16 *p_a1h, *p_a1l, *p_a2h, *p_a2l;
    __nv_bfloat16 *p_w1h, *p_w1l, *p_w2h, *p_w2l;
    cudaGetSymbolAddress((void**)&p_act1h, g_act1h);
    cudaGetSymbolAddress((void**)&p_a1h, g_a1h);
    cudaGetSymbolAddress((void**)&p_a1l, g_a1l);
    cudaGetSymbolAddress((void**)&p_a2h, g_a2h);
    cudaGetSymbolAddress((void**)&p_a2l, g_a2l);
    cudaGetSymbolAddress((void**)&p_w1h, g_w1h);
    cudaGetSymbolAddress((void**)&p_w1l, g_w1l);
    cudaGetSymbolAddress((void**)&p_w2h, g_w2h);
    cudaGetSymbolAddress((void**)&p_w2l, g_w2l);

    const int TB = 256;
    const int SMEM = 2 * STAGE;   // 80 KB

    cudaFuncSetAttribute(gemm_kernel<false>,
                         cudaFuncAttributeMaxDynamicSharedMemorySize, SMEM);
    cudaFuncSetAttribute(gemm_kernel<true>,
                         cudaFuncAttributeMaxDynamicSharedMemorySize, SMEM);

    deg_kernel<<<(N_EDGES + TB - 1) / TB, TB>>>(ei, x);        // #1 (+xconv)
    scan_kernel<<<NB_SCAN, 256>>>();                           // #2 (lookback)
    fill_kernel<<<(N_EDGES + TB - 1) / TB, TB>>>(ei);          // #3
    agg1_kernel<<<(N_NODES + 7) / 8, 256>>>();                 // #4 <- profiled
    wsplit_kernel<<<(K1 * H + H * H + TB - 1) / TB, TB>>>(W1, W2);  // #5

    dim3 gemm_grid((N_NODES + 127) / 128, H / 128);

    gemm_kernel<false><<<gemm_grid, 512, SMEM>>>(p_a1h, p_a1l, p_w1h, p_w1l, b1,
                                                 p_act1h, batch, N_NODES, K1);  // #6

    agg2_kernel<<<(2 * N_NODES + 7) / 8, 256>>>();             // #7 (2 tasks/node)
    gemm_kernel<true><<<gemm_grid, 512, SMEM>>>(p_a2h, p_a2l, p_w2h, p_w2l, b2,
                                                nullptr, batch, N_NODES, H);    // #8

    classifier_kernel<<<N_GRAPHS, NCLS>>>(Wc, bc, batch, out); // #9 (+cleanup)
}

// round 16
// speedup vs baseline: 1.0431x; 1.0431x over previous
#include <cuda_runtime.h>
#include <cuda_bf16.h>
#include <cuda_fp16.h>
#include <math.h>
#include <stdint.h>

#define N_NODES  100000
#define N_EDGES  1600000
#define N_GRAPHS 2048
#define H        256
#define K1       128
#define NCLS     64
#define NB_SCAN  ((N_NODES + 255) / 256)   // 391

// ---------------- scratch (device globals; zero-initialized at load) -------
__device__ int   g_degi[N_NODES];
__device__ int   g_rowptr[N_NODES + 1];
__device__ int   g_cur[N_NODES];
__device__ volatile unsigned long long g_scanst[NB_SCAN];  // lookback state
__device__ float g_dinv[N_NODES];
__device__ int2  g_edge[N_EDGES];                  // {src*32, norm as int}
__device__ __half g_xh [(size_t)N_NODES * K1];     // fp16 copy of x
__device__ __half g_act1h[(size_t)N_NODES * H];    // fp16 act1
__device__ __nv_bfloat16 g_a1h[(size_t)N_NODES * K1];
__device__ __nv_bfloat16 g_a1l[(size_t)N_NODES * K1];
__device__ __nv_bfloat16 g_a2h[(size_t)N_NODES * H];
__device__ __nv_bfloat16 g_a2l[(size_t)N_NODES * H];
__device__ __nv_bfloat16 g_w1h[H * K1];
__device__ __nv_bfloat16 g_w1l[H * K1];
__device__ __nv_bfloat16 g_w2h[H * H];
__device__ __nv_bfloat16 g_w2l[H * H];
__device__ float g_sums[N_GRAPHS * H];

__device__ __forceinline__ uint32_t s2u(const void* p) {
    return (uint32_t)__cvta_generic_to_shared(p);
}
__device__ __forceinline__ void cpa16(uint32_t dst, const void* src, int nbytes) {
    asm volatile("cp.async.cg.shared.global [%0], [%1], 16, %2;"
                 :: "r"(dst), "l"(src), "r"(nbytes));
}

// ---------------- #1: degree histogram + x->fp16 (full occupancy) ------------
__global__ void deg_kernel(const int* __restrict__ ei, const float* __restrict__ x) {
    int e = blockIdx.x * blockDim.x + threadIdx.x;
    if (e < N_EDGES) atomicAdd(&g_degi[ei[N_EDGES + e]], 1);
    for (int t = e; t < N_NODES * (K1 / 4); t += N_EDGES) {
        float4 v = ((const float4*)x)[t];
        __half2 a = __floats2half2_rn(v.x, v.y);
        __half2 b = __floats2half2_rn(v.z, v.w);
        ((uint2*)g_xh)[t] = make_uint2(*(uint32_t*)&a, *(uint32_t*)&b);
    }
}

// ---------------- #2: single-pass scan (decoupled lookback) + dinv -----------
__global__ void scan_kernel() {
    __shared__ int sh[256];
    __shared__ int s_pref;
    int b = blockIdx.x, t = threadIdx.x;
    int i = b * 256 + t;
    int v = (i < N_NODES) ? g_degi[i] : 0;
    if (i < N_NODES) g_dinv[i] = rsqrtf((float)(v + 1));
    sh[t] = v;
    __syncthreads();
    for (int off = 1; off < 256; off <<= 1) {
        int tmp = (t >= off) ? sh[t - off] : 0;
        __syncthreads();
        sh[t] += tmp;
        __syncthreads();
    }
    int excl = sh[t] - v;
    if (t == 255) {
        int total = sh[255];
        if (b == 0) {
            g_scanst[0] = ((unsigned long long)total << 2) | 2ull;
            __threadfence();
            s_pref = 0;
        } else {
            g_scanst[b] = ((unsigned long long)total << 2) | 1ull;
            __threadfence();
            int sum = 0;
            for (int p = b - 1; p >= 0; ) {
                unsigned long long s;
                do { s = g_scanst[p]; } while ((s & 3ull) == 0ull);
                sum += (int)(s >> 2);
                if ((s & 3ull) == 2ull) break;
                p--;
            }
            g_scanst[b] = ((unsigned long long)(sum + total) << 2) | 2ull;
            __threadfence();
            s_pref = sum;
        }
    }
    __syncthreads();
    if (i < N_NODES) {
        int r = s_pref + excl;
        g_rowptr[i] = r;
        g_cur[i] = r;
    }
    if (i == 0) g_rowptr[N_NODES] = N_EDGES;
}

// ---------------- #3: CSR fill (packed, pre-scaled edge records) -------------
__global__ void fill_kernel(const int* __restrict__ ei) {
    int e = blockIdx.x * blockDim.x + threadIdx.x;
    if (e >= N_EDGES) return;
    int s = ei[e];
    int d = ei[N_EDGES + e];
    int pos = atomicAdd(&g_cur[d], 1);
    float nrm = g_dinv[s] * g_dinv[d];
    g_edge[pos] = make_int2(s * 32, __float_as_int(nrm));
}

// ---------------- weight transposes + bf16 hi/lo splits ----------------------
__global__ void wsplit_kernel(const float* __restrict__ W1,
                              const float* __restrict__ W2) {
    int idx = blockIdx.x * blockDim.x + threadIdx.x;
    const float* W;
    __nv_bfloat16 *Wh, *Wl;
    int K, local;
    if (idx < K1 * H) { W = W1; Wh = g_w1h; Wl = g_w1l; K = K1; local = idx; }
    else if (idx < K1 * H + H * H) {
        W = W2; Wh = g_w2h; Wl = g_w2l; K = H; local = idx - K1 * H;
    } else return;
    int k = local / H, n = local % H;
    float w = W[local];
    __nv_bfloat16 hi = __float2bfloat16_rn(w);
    float lo = w - __bfloat162float(hi);
    Wh[n * K + k] = hi;
    Wl[n * K + k] = __float2bfloat16_rn(lo);
}

// ---------------- split helpers ----------------------------------------------
__device__ __forceinline__ void split4(float4 v, uint2& hi, uint2& lo) {
    __nv_bfloat16 hx = __float2bfloat16_rn(v.x);
    __nv_bfloat16 hy = __float2bfloat16_rn(v.y);
    __nv_bfloat16 hz = __float2bfloat16_rn(v.z);
    __nv_bfloat16 hw = __float2bfloat16_rn(v.w);
    __nv_bfloat162 h01 = __halves2bfloat162(hx, hy);
    __nv_bfloat162 h23 = __halves2bfloat162(hz, hw);
    __nv_bfloat162 l01 = __halves2bfloat162(
        __float2bfloat16_rn(v.x - __bfloat162float(hx)),
        __float2bfloat16_rn(v.y - __bfloat162float(hy)));
    __nv_bfloat162 l23 = __halves2bfloat162(
        __float2bfloat16_rn(v.z - __bfloat162float(hz)),
        __float2bfloat16_rn(v.w - __bfloat162float(hw)));
    hi = make_uint2(*(uint32_t*)&h01, *(uint32_t*)&h23);
    lo = make_uint2(*(uint32_t*)&l01, *(uint32_t*)&l23);
}

__device__ __forceinline__ float4 h4_to_f4(uint2 u) {
    __half2 a = *(__half2*)&u.x;
    __half2 b = *(__half2*)&u.y;
    float2 fa = __half22float2(a);
    float2 fb = __half22float2(b);
    return make_float4(fa.x, fa.y, fb.x, fb.y);
}

// ---------------- #4: aggregation 1 (width 128, 8 edges in flight) -----------
__global__ __launch_bounds__(256, 8) void agg1_kernel() {
    int node = blockIdx.x * 8 + (threadIdx.x >> 5);
    if (node >= N_NODES) return;
    int lane = threadIdx.x & 31;
    const uint2* Xl = (const uint2*)g_xh + lane;   // lane offset hoisted

    float di = g_dinv[node];
    float sl = di * di;
    float4 a = h4_to_f4(Xl[node * 32]);
    float4 acc = make_float4(a.x * sl, a.y * sl, a.z * sl, a.w * sl);

    int i = g_rowptr[node], end = g_rowptr[node + 1];
    for (; i + 8 <= end; i += 8) {
        uint2 u[8];
        float w[8];
        #pragma unroll
        for (int q = 0; q < 8; q++) {
            int2 e = g_edge[i + q];        // one LDG.64: {src*32, norm}
            w[q] = __int_as_float(e.y);
            u[q] = Xl[e.x];
        }
        #pragma unroll
        for (int q = 0; q < 8; q++) {
            float4 v = h4_to_f4(u[q]);
            acc.x += v.x * w[q]; acc.y += v.y * w[q];
            acc.z += v.z * w[q]; acc.w += v.w * w[q];
        }
    }
    for (; i < end; i++) {
        int2 e = g_edge[i];
        float w = __int_as_float(e.y);
        float4 v = h4_to_f4(Xl[e.x]);
        acc.x += v.x*w; acc.y += v.y*w; acc.z += v.z*w; acc.w += v.w*w;
    }
    uint2 hi, lo;
    split4(acc, hi, lo);
    ((uint2*)g_a1h)[(size_t)node * 32 + lane] = hi;
    ((uint2*)g_a1l)[(size_t)node * 32 + lane] = lo;
}

// ---------------- aggregation 2 (width 256, 4 edges in flight) ---------------
__global__ __launch_bounds__(256, 8) void agg2_kernel() {
    int node = blockIdx.x * 8 + (threadIdx.x >> 5);
    if (node >= N_NODES) return;
    int lane = threadIdx.x & 31;
    const uint4* Xl = (const uint4*)g_act1h + lane;

    float di = g_dinv[node];
    float sl = di * di;
    uint4 au = Xl[(size_t)node * 32];
    float4 a0 = h4_to_f4(make_uint2(au.x, au.y));
    float4 a1 = h4_to_f4(make_uint2(au.z, au.w));
    float4 acc0 = make_float4(a0.x*sl, a0.y*sl, a0.z*sl, a0.w*sl);
    float4 acc1 = make_float4(a1.x*sl, a1.y*sl, a1.z*sl, a1.w*sl);

    int i = g_rowptr[node], end = g_rowptr[node + 1];
    for (; i + 4 <= end; i += 4) {
        uint4 u[4];
        float w[4];
        #pragma unroll
        for (int q = 0; q < 4; q++) {
            int2 e = g_edge[i + q];
            w[q] = __int_as_float(e.y);
            u[q] = Xl[e.x];               // e.x = src*32 = uint4 row offset
        }
        #pragma unroll
        for (int q = 0; q < 4; q++) {
            float4 v0 = h4_to_f4(make_uint2(u[q].x, u[q].y));
            float4 v1 = h4_to_f4(make_uint2(u[q].z, u[q].w));
            acc0.x += v0.x*w[q]; acc0.y += v0.y*w[q];
            acc0.z += v0.z*w[q]; acc0.w += v0.w*w[q];
            acc1.x += v1.x*w[q]; acc1.y += v1.y*w[q];
            acc1.z += v1.z*w[q]; acc1.w += v1.w*w[q];
        }
    }
    for (; i < end; i++) {
        int2 e = g_edge[i];
        float w = __int_as_float(e.y);
        uint4 u = Xl[e.x];
        float4 v0 = h4_to_f4(make_uint2(u.x, u.y));
        float4 v1 = h4_to_f4(make_uint2(u.z, u.w));
        acc0.x += v0.x*w; acc0.y += v0.y*w; acc0.z += v0.z*w; acc0.w += v0.w*w;
        acc1.x += v1.x*w; acc1.y += v1.y*w; acc1.z += v1.z*w; acc1.w += v1.w*w;
    }
    uint2 hi, lo;
    split4(acc0, hi, lo);
    ((uint2*)g_a2h)[(size_t)node * 64 + lane] = hi;
    ((uint2*)g_a2l)[(size_t)node * 64 + lane] = lo;
    split4(acc1, hi, lo);
    ((uint2*)g_a2h)[(size_t)node * 64 + 32 + lane] = hi;
    ((uint2*)g_a2l)[(size_t)node * 64 + 32 + lane] = lo;
}

// ---------------- bf16-split tensor-core GEMM (pipelined, mma.sync) ----------
#define ROWB 80
#define OFF_AL 10240
#define OFF_BH 20480
#define OFF_BL 30720
#define STAGE  40960

template <bool POOL>
__global__ __launch_bounds__(512, 1) void gemm_kernel(
    const __nv_bfloat16* __restrict__ Ahg,
    const __nv_bfloat16* __restrict__ Alg,
    const __nv_bfloat16* __restrict__ Wth,
    const __nv_bfloat16* __restrict__ Wtl,
    const float* __restrict__ bias,
    __half* __restrict__ outh,
    const int* __restrict__ batch,
    int M, int K)
{
    extern __shared__ __align__(16) char smem[];
    const uint32_t sbase = s2u(smem);

    const int tid  = threadIdx.x;
    const int lane = tid & 31;
    const int wid  = tid >> 5;
    const int wm   = wid & 3;
    const int wn   = wid >> 2;
    const int bm   = blockIdx.x * 128;
    const int bn   = blockIdx.y * 128;

    const int lrow = tid >> 2;
    const int lcc  = tid & 3;
    const int arow_g = bm + lrow;
    const int avalid = (arow_g < M) ? 16 : 0;

    float acc[2][4][4];
    #pragma unroll
    for (int i = 0; i < 2; i++)
        #pragma unroll
        for (int j = 0; j < 4; j++)
            #pragma unroll
            for (int l = 0; l < 4; l++) acc[i][j][l] = 0.0f;

    const int T = K / 32;

    auto load_stage = [&](int t, int s) {
        int kk = t * 32;
        uint32_t base = sbase + s * STAGE + lrow * ROWB + lcc * 16;
        cpa16(base,          Ahg + (size_t)arow_g * K + kk + lcc * 8, avalid);
        cpa16(base + OFF_AL, Alg + (size_t)arow_g * K + kk + lcc * 8, avalid);
        cpa16(base + OFF_BH, Wth + (size_t)(bn + lrow) * K + kk + lcc * 8, 16);
        cpa16(base + OFF_BL, Wtl + (size_t)(bn + lrow) * K + kk + lcc * 8, 16);
        asm volatile("cp.async.commit_group;");
    };

    load_stage(0, 0);

    const int grp = lane >> 3, lr = lane & 7;

    for (int t = 0; t < T; t++) {
        int cur = t & 1;
        if (t + 1 < T) {
            load_stage(t + 1, cur ^ 1);
            asm volatile("cp.async.wait_group 1;");
        } else {
            asm volatile("cp.async.wait_group 0;");
        }
        __syncthreads();

        uint32_t sA = sbase + cur * STAGE;
        uint32_t sB = sA + OFF_BH;

        #pragma unroll
        for (int ks = 0; ks < 2; ks++) {
            const int kb = ks * 32;
            uint32_t fah[2][4], fal[2][4], fbh[8], fbl[8];
            #pragma unroll
            for (int mt = 0; mt < 2; mt++) {
                int arow = wm * 32 + mt * 16 + lr + ((grp & 1) ? 8 : 0);
                uint32_t ad = sA + arow * ROWB + kb + ((grp & 2) ? 16 : 0);
                asm volatile("ldmatrix.sync.aligned.m8n8.x4.shared.b16 {%0,%1,%2,%3}, [%4];"
                             : "=r"(fah[mt][0]), "=r"(fah[mt][1]), "=r"(fah[mt][2]), "=r"(fah[mt][3])
                             : "r"(ad));
                asm volatile("ldmatrix.sync.aligned.m8n8.x4.shared.b16 {%0,%1,%2,%3}, [%4];"
                             : "=r"(fal[mt][0]), "=r"(fal[mt][1]), "=r"(fal[mt][2]), "=r"(fal[mt][3])
                             : "r"(ad + OFF_AL));
            }
            #pragma unroll
            for (int bp = 0; bp < 2; bp++) {
                int brow = wn * 32 + bp * 16 + lr + ((grp & 2) ? 8 : 0);
                uint32_t bd = sB + brow * ROWB + kb + ((grp & 1) ? 16 : 0);
                asm volatile("ldmatrix.sync.aligned.m8n8.x4.shared.b16 {%0,%1,%2,%3}, [%4];"
                             : "=r"(fbh[bp*4+0]), "=r"(fbh[bp*4+1]), "=r"(fbh[bp*4+2]), "=r"(fbh[bp*4+3])
                             : "r"(bd));
                asm volatile("ldmatrix.sync.aligned.m8n8.x4.shared.b16 {%0,%1,%2,%3}, [%4];"
                             : "=r"(fbl[bp*4+0]), "=r"(fbl[bp*4+1]), "=r"(fbl[bp*4+2]), "=r"(fbl[bp*4+3])
                             : "r"(bd + (OFF_BL - OFF_BH)));
            }
            #pragma unroll
            for (int mt = 0; mt < 2; mt++) {
                #pragma unroll
                for (int nt = 0; nt < 4; nt++) {
                    float* c = acc[mt][nt];
                    uint32_t b0 = fbh[nt*2], b1 = fbh[nt*2+1];
                    uint32_t l0 = fbl[nt*2], l1 = fbl[nt*2+1];
                    asm volatile("mma.sync.aligned.m16n8k16.row.col.f32.bf16.bf16.f32 "
                                 "{%0,%1,%2,%3}, {%4,%5,%6,%7}, {%8,%9}, {%0,%1,%2,%3};"
                                 : "+f"(c[0]), "+f"(c[1]), "+f"(c[2]), "+f"(c[3])
                                 : "r"(fah[mt][0]), "r"(fah[mt][1]), "r"(fah[mt][2]), "r"(fah[mt][3]),
                                   "r"(b0), "r"(b1));
                    asm volatile("mma.sync.aligned.m16n8k16.row.col.f32.bf16.bf16.f32 "
                                 "{%0,%1,%2,%3}, {%4,%5,%6,%7}, {%8,%9}, {%0,%1,%2,%3};"
                                 : "+f"(c[0]), "+f"(c[1]), "+f"(c[2]), "+f"(c[3])
                                 : "r"(fah[mt][0]), "r"(fah[mt][1]), "r"(fah[mt][2]), "r"(fah[mt][3]),
                                   "r"(l0), "r"(l1));
                    asm volatile("mma.sync.aligned.m16n8k16.row.col.f32.bf16.bf16.f32 "
                                 "{%0,%1,%2,%3}, {%4,%5,%6,%7}, {%8,%9}, {%0,%1,%2,%3};"
                                 : "+f"(c[0]), "+f"(c[1]), "+f"(c[2]), "+f"(c[3])
                                 : "r"(fal[mt][0]), "r"(fal[mt][1]), "r"(fal[mt][2]), "r"(fal[mt][3]),
                                   "r"(b0), "r"(b1));
                }
            }
        }
        __syncthreads();
    }

    const int qr = lane >> 2;
    const int qc = (lane & 3) * 2;
    #pragma unroll
    for (int mt = 0; mt < 2; mt++) {
        int row0 = bm + wm * 32 + mt * 16 + qr;
        int row1 = row0 + 8;
        int bt0 = 0, bt1 = 0;
        if (POOL) {
            bt0 = (row0 < M) ? batch[row0] : 0;
            bt1 = (row1 < M) ? batch[row1] : 0;
        }
        #pragma unroll
        for (int nt = 0; nt < 4; nt++) {
            int col = bn + wn * 32 + nt * 8 + qc;
            float bx = bias[col], by = bias[col + 1];
            float v00 = fmaxf(acc[mt][nt][0] + bx, 0.f);
            float v01 = fmaxf(acc[mt][nt][1] + by, 0.f);
            float v10 = fmaxf(acc[mt][nt][2] + bx, 0.f);
            float v11 = fmaxf(acc[mt][nt][3] + by, 0.f);
            if (POOL) {
                if (row0 < M) {
                    float* p = &g_sums[(size_t)bt0 * H + col];
                    asm volatile("red.global.add.v2.f32 [%0], {%1,%2};"
                                 :: "l"(p), "f"(v00), "f"(v01) : "memory");
                }
                if (row1 < M) {
                    float* p = &g_sums[(size_t)bt1 * H + col];
                    asm volatile("red.global.add.v2.f32 [%0], {%1,%2};"
                                 :: "l"(p), "f"(v10), "f"(v11) : "memory");
                }
            } else {
                if (row0 < M)
                    *(__half2*)&outh[(size_t)row0 * H + col] = __floats2half2_rn(v00, v01);
                if (row1 < M)
                    *(__half2*)&outh[(size_t)row1 * H + col] = __floats2half2_rn(v10, v11);
            }
        }
    }
}

// ---------------- classifier + log_softmax + cleanup (fused) -----------------
__device__ __forceinline__ int lbound(const int* __restrict__ a, int key) {
    int lo = 0, hi = N_NODES;
    while (lo < hi) {
        int m = (lo + hi) >> 1;
        if (a[m] < key) lo = m + 1; else hi = m;
    }
    return lo;
}

__global__ __launch_bounds__(64) void classifier_kernel(
    const float* __restrict__ Wc, const float* __restrict__ bc,
    const int* __restrict__ batch, float* __restrict__ out)
{
    int g = blockIdx.x;
    int t = threadIdx.x;
    __shared__ float gv[H];
    __shared__ float lg[NCLS];
    __shared__ int s_lo, s_hi;

    if (t == 0) s_lo = lbound(batch, g);
    if (t == 1) s_hi = lbound(batch, g + 1);

    for (int k = t; k < H; k += NCLS) gv[k] = g_sums[g * H + k];
    __syncthreads();

    float inv = 1.0f / fmaxf((float)(s_hi - s_lo), 1.0f);

    float acc = bc[t];
    #pragma unroll 8
    for (int k = 0; k < H; k++) acc += gv[k] * inv * Wc[k * NCLS + t];
    lg[t] = acc;
    __syncthreads();

    float m = -INFINITY;
    #pragma unroll
    for (int i = 0; i < NCLS; i++) m = fmaxf(m, lg[i]);
    float s = 0.0f;
    #pragma unroll
    for (int i = 0; i < NCLS; i++) s += expf(lg[i] - m);
    out[g * NCLS + t] = acc - m - logf(s);

    // ---- cleanup for next graph-replayed call ----
    for (int k = t; k < H; k += NCLS) g_sums[g * H + k] = 0.0f;
    int flat = g * NCLS + t;                 // 0 .. 131071
    if (flat < N_NODES) g_degi[flat] = 0;
    if (flat < NB_SCAN) g_scanst[flat] = 0ull;
}

// ---------------- launch ------------------------------------------------------
extern "C" void kernel_launch(void* const* d_in, const int* in_sizes, int n_in,
                              void* d_out, int out_size)
{
    const float* x     = (const float*)d_in[0];
    const int*   ei    = (const int*)d_in[1];
    const int*   batch = (const int*)d_in[2];
    const float* W1    = (const float*)d_in[3];
    const float* b1    = (const float*)d_in[4];
    const float* W2    = (const float*)d_in[5];
    const float* b2    = (const float*)d_in[6];
    const float* Wc    = (const float*)d_in[7];
    const float* bc    = (const float*)d_in[8];
    float* out = (float*)d_out;

    __half *p_act1h;
    __nv_bfloat16 *p_a1h, *p_a1l, *p_a2h, *p_a2l;
    __nv_bfloat16 *p_w1h, *p_w1l, *p_w2h, *p_w2l;
    cudaGetSymbolAddress((void**)&p_act1h, g_act1h);
    cudaGetSymbolAddress((void**)&p_a1h, g_a1h);
    cudaGetSymbolAddress((void**)&p_a1l, g_a1l);
    cudaGetSymbolAddress((void**)&p_a2h, g_a2h);
    cudaGetSymbolAddress((void**)&p_a2l, g_a2l);
    cudaGetSymbolAddress((void**)&p_w1h, g_w1h);
    cudaGetSymbolAddress((void**)&p_w1l, g_w1l);
    cudaGetSymbolAddress((void**)&p_w2h, g_w2h);
    cudaGetSymbolAddress((void**)&p_w2l, g_w2l);

    const int TB = 256;
    const int SMEM = 2 * STAGE;   // 80 KB

    cudaFuncSetAttribute(gemm_kernel<false>,
                         cudaFuncAttributeMaxDynamicSharedMemorySize, SMEM);
    cudaFuncSetAttribute(gemm_kernel<true>,
                         cudaFuncAttributeMaxDynamicSharedMemorySize, SMEM);

    deg_kernel<<<(N_EDGES + TB - 1) / TB, TB>>>(ei, x);        // #1 (+xconv)
    scan_kernel<<<NB_SCAN, 256>>>();                           // #2 (lookback)
    fill_kernel<<<(N_EDGES + TB - 1) / TB, TB>>>(ei);          // #3
    agg1_kernel<<<(N_NODES + 7) / 8, 256>>>();                 // #4 <- profiled
    wsplit_kernel<<<(K1 * H + H * H + TB - 1) / TB, TB>>>(W1, W2);  // #5

    dim3 gemm_grid((N_NODES + 127) / 128, H / 128);

    gemm_kernel<false><<<gemm_grid, 512, SMEM>>>(p_a1h, p_a1l, p_w1h, p_w1l, b1,
                                                 p_act1h, batch, N_NODES, K1);  // #6

    agg2_kernel<<<(N_NODES + 7) / 8, 256>>>();                 // #7
    gemm_kernel<true><<<gemm_grid, 512, SMEM>>>(p_a2h, p_a2l, p_w2h, p_w2l, b2,
                                                nullptr, batch, N_NODES, H);    // #8

    classifier_kernel<<<N_GRAPHS, NCLS>>>(Wc, bc, batch, out); // #9 (+cleanup)
}